// round 15
// baseline (speedup 1.0000x reference)
#include <cuda_runtime.h>
#include <cstdint>

// Problem constants (fixed by setup_inputs)
#define BB 8
#define NN 8192
#define NPOINT 1024
#define NSAMPLE 32
#define DD 64
#define R2 0.0625f
#define OUTCH 67  // 3 + 64

#define FPS_T 512               // threads per block (uniform)
#define CL 4                    // cluster size = FPS CTAs per batch
#define NFPS (BB * CL)          // 32 FPS blocks
#define PTS_CTA (NN / CL)       // 2048 points per FPS CTA
#define NPREP 128               // prep blocks (512 pts each)
#define BALLW 16                // warps (= centroids) per ball block
#define NBALL (BB * NPOINT / BALLW)   // 512 ball blocks
#define DYN_SMEM 196608         // 192KB for every block -> 1 block/SM
#define PUB 16                  // FPS progress publish granularity

using u64 = unsigned long long;
using u32 = unsigned int;

// ---- packed f32x2 helpers (per-lane IEEE RN, bit-identical to scalar RN ops)
__device__ __forceinline__ u64 pk2(float lo, float hi) {
    u64 r; asm("mov.b64 %0, {%1,%2};" : "=l"(r) : "f"(lo), "f"(hi)); return r;
}
__device__ __forceinline__ void up2(u64 v, float& lo, float& hi) {
    asm("mov.b64 {%0,%1}, %2;" : "=f"(lo), "=f"(hi) : "l"(v));
}
__device__ __forceinline__ u64 add2(u64 a, u64 b) {
    u64 r; asm("add.rn.f32x2 %0, %1, %2;" : "=l"(r) : "l"(a), "l"(b)); return r;
}
__device__ __forceinline__ u64 mul2(u64 a, u64 b) {
    u64 r; asm("mul.rn.f32x2 %0, %1, %2;" : "=l"(r) : "l"(a), "l"(b)); return r;
}
__device__ __forceinline__ u32 smem_u32(const void* p) {
    u32 a;
    asm("{ .reg .u64 t; cvta.to.shared.u64 t, %1; cvt.u32.u64 %0, t; }"
        : "=r"(a) : "l"(p));
    return a;
}
__device__ __forceinline__ u32 mapa_u32(u32 a, u32 rank) {
    u32 o; asm("mapa.shared::cluster.u32 %0, %1, %2;" : "=r"(o) : "r"(a), "r"(rank));
    return o;
}
__device__ __forceinline__ void vsts64(u32 a, u64 v) {
    asm volatile("st.volatile.shared.b64 [%0], %1;" :: "r"(a), "l"(v) : "memory");
}
__device__ __forceinline__ void st_cluster64(u32 a, u64 v) {
    asm volatile("st.shared::cluster.b64 [%0], %1;" :: "r"(a), "l"(v) : "memory");
}

// ---------------------------------------------------------------------------
// Device scratch + producer/consumer counters (zeroed per launch by init)
// ---------------------------------------------------------------------------
__device__ float4 g_pk[BB * NN];   // packed {x,y,z,|p|^2}
__device__ int    g_progress[BB];  // FPS steps published per batch
__device__ int    g_prep_done;     // prep blocks completed

__global__ void init_kernel() {
    if (threadIdx.x < BB) g_progress[threadIdx.x] = 0;
    if (threadIdx.x == BB) g_prep_done = 0;
}

// ---------------------------------------------------------------------------
// Mega kernel, cluster size 4. Blocks 0..31: FPS. 32..159: prep. 160..671:
// ball. FPS clusters are exactly blocks 4c..4c+3, so prep/ball clusters never
// execute cluster ops.
//
// FPS: BARRIER-FREE warp-key all-to-all (R12 topology — measured optimum:
// all-warps-poll at CL=8 saturates smem ports, designated-poller at CL=4
// adds a serial hop; direct all-to-all at CL=4 wins). Two refinements:
//  (1) parallel posting: REDUX results are warp-uniform, lanes 0..3 each
//      post the key to one CTA (no lane0 4-store serialization).
//  (2) per-lane polling: each lane spins only until ITS OWN 2 slots carry
//      the step tag (no __all_sync per iteration); the subsequent REDUX is
//      the warp reconvergence point.
//  - key = (val<<32) | ((8191-idx)<<2) | (it&3); aligned 8B store = atomic;
//    key IS the payload -> no fence of any scope, no per-step barrier.
//  - max key = max value, ties -> max(8191-idx) = smallest index =
//    jnp.argmax first-occurrence (tag bits equal across a step).
//  - slot-reuse safety: double-buffered by it&1 with 2-bit tag; buffer b's
//    consecutive users are steps it, it+2 with different tags; a writer
//    reaches it+2 only after consuming it+1, which transitively requires
//    every warp to have consumed it. Slots init to tag=2; one startup
//    cluster.sync covers initialization.
// ---------------------------------------------------------------------------
__global__ void __launch_bounds__(FPS_T, 1) __cluster_dims__(CL, 1, 1)
mega_kernel(const float* __restrict__ xyz, const float* __restrict__ points,
            float* __restrict__ new_xyz, float* __restrict__ new_points) {
    extern __shared__ u64 dynsmem[];
    const int bid = blockIdx.x;
    const int tid = threadIdx.x;
    const int lane = tid & 31;
    const int w    = tid >> 5;

    // =========================== PREP path ================================
    if (bid >= NFPS && bid < NFPS + NPREP) {
        int i = (bid - NFPS) * FPS_T + tid;      // 0 .. BB*NN-1
        const float* p = xyz + (size_t)i * 3;
        float x = __ldg(p + 0), y = __ldg(p + 1), z = __ldg(p + 2);
        float dn = __fadd_rn(__fadd_rn(__fmul_rn(x, x), __fmul_rn(y, y)),
                             __fmul_rn(z, z));
        g_pk[i] = make_float4(x, y, z, dn);
        __syncthreads();
        if (tid == 0) {
            int dummy;
            asm volatile("atom.add.release.gpu.global.s32 %0, [%1], 1;"
                         : "=r"(dummy) : "l"(&g_prep_done) : "memory");
        }
        return;
    }

    // ============================ FPS path =================================
    if (bid < NFPS) {
        u64* sneg = dynsmem;                      // [NN*3] negated dup table
        __shared__ u64 slots[2][64];              // [buf][cta*16+warp]

        const int b       = bid >> 2;
        const u32 rank    = bid & 3;
        const int pbase   = rank * PTS_CTA;
        const float* xb   = xyz + (size_t)b * NN * 3;

        // full-batch negated table (every CTA keeps its own copy)
        for (int j = tid; j < NN; j += FPS_T) {
            float x = __ldg(xb + j * 3 + 0);
            float y = __ldg(xb + j * 3 + 1);
            float z = __ldg(xb + j * 3 + 2);
            sneg[3 * j + 0] = pk2(-x, -x);
            sneg[3 * j + 1] = pk2(-y, -y);
            sneg[3 * j + 2] = pk2(-z, -z);
        }
        // own 4 points (k = 0..3 at pbase + tid + k*512), packed by pairs
        u64 px2[2], py2[2], pz2[2];
        u32 du[4];
#pragma unroll
        for (int p = 0; p < 2; p++) {
            int j0 = pbase + tid + (2 * p) * FPS_T;
            int j1 = pbase + tid + (2 * p + 1) * FPS_T;
            px2[p] = pk2(__ldg(xb + j0 * 3 + 0), __ldg(xb + j1 * 3 + 0));
            py2[p] = pk2(__ldg(xb + j0 * 3 + 1), __ldg(xb + j1 * 3 + 1));
            pz2[p] = pk2(__ldg(xb + j0 * 3 + 2), __ldg(xb + j1 * 3 + 2));
        }
#pragma unroll
        for (int k = 0; k < 4; k++) du[k] = __float_as_uint(1e10f);

        const u32 rbase = smem_u32(&slots[0][0]);
        if (tid < 64) {                    // init both buffers with tag=2
            vsts64(rbase + tid * 8u, 2ull);
            vsts64(rbase + 512u + tid * 8u, 2ull);
        }
        // per-lane target CTA base (lanes 0..3 post in parallel; mapa to own
        // rank is a valid local address)
        const u32 tgt = mapa_u32(rbase, (u32)(lane & 3));

        __syncthreads();
        // one-time cluster rendezvous: all CTAs' slots initialized before any
        // remote key write can land
        asm volatile("barrier.cluster.arrive.aligned;" ::: "memory");
        asm volatile("barrier.cluster.wait.aligned;"   ::: "memory");

        u64 ncx = sneg[0], ncy = sneg[1], ncz = sneg[2];   // centroid 0, neg
        float* ob = new_xyz + (size_t)b * NPOINT * 3;
        const bool emitter = (rank == 0) && (tid == FPS_T - 1);
        const u32 myslot = (u32)((rank * 16 + w) << 3);

        for (int it = 0; it < NPOINT; it++) {
            if (emitter) {   // emit un-negated centroid (sign XOR: exact)
                float lx, t0, ly, t1, lz, t2;
                up2(ncx, lx, t0); up2(ncy, ly, t1); up2(ncz, lz, t2);
                ob[it * 3 + 0] = __uint_as_float(__float_as_uint(lx) ^ 0x80000000u);
                ob[it * 3 + 1] = __uint_as_float(__float_as_uint(ly) ^ 0x80000000u);
                ob[it * 3 + 2] = __uint_as_float(__float_as_uint(lz) ^ 0x80000000u);
                if (((it + 1) & (PUB - 1)) == 0) {
                    asm volatile("st.release.gpu.global.s32 [%0], %1;"
                                 :: "l"(&g_progress[b]), "r"(it + 1) : "memory");
                }
            }
            if (it == NPOINT - 1) break;

            // exact jnp order: d = ((dx*dx+dy*dy)+dz*dz); dist = min(dist, d)
#pragma unroll
            for (int p = 0; p < 2; p++) {
                u64 dx = add2(px2[p], ncx);
                u64 dy = add2(py2[p], ncy);
                u64 dz = add2(pz2[p], ncz);
                u64 dd = add2(add2(mul2(dx, dx), mul2(dy, dy)), mul2(dz, dz));
                float a, bq; up2(dd, a, bq);
                du[2 * p]     = min(du[2 * p],     __float_as_uint(a));
                du[2 * p + 1] = min(du[2 * p + 1], __float_as_uint(bq));
            }

            // argmax tree over 4 ('>=' keeps left -> smallest k on ties)
            u32 v01 = max(du[0], du[1]); int k01 = (du[0] >= du[1]) ? 0 : 1;
            u32 v23 = max(du[2], du[3]); int k23 = (du[2] >= du[3]) ? 2 : 3;
            u32 vb  = max(v01, v23);     int kk  = (v01 >= v23) ? k01 : k23;
            u32 idx = (u32)(pbase + tid + kk * FPS_T);

            // warp: max value, then min index among holders of the max
            u32 wmax = __reduce_max_sync(0xffffffffu, vb);
            u32 cand = (vb == wmax) ? idx : 0xffffffffu;
            u32 ci   = __reduce_min_sync(0xffffffffu, cand);

            const u32 boff = (u32)((it & 1) << 9);
            const u32 tag  = (u32)(it & 3);
            // lanes 0..3 each post the (warp-uniform) key to one CTA
            u64 key = ((u64)wmax << 32) | (u64)(((8191u - ci) << 2) | tag);
            if (lane < 4) st_cluster64(tgt + boff + myslot, key);

            // per-lane poll of this lane's 2 slots; REDUX below reconverges
            const u32 pa = rbase + boff + (u32)(lane << 4);
            u64 k0, k1;
            for (;;) {
                asm volatile("ld.volatile.shared.v2.u64 {%0,%1}, [%2];"
                             : "=l"(k0), "=l"(k1) : "r"(pa));
                if ((((u32)k0 & 3u) == tag) & (((u32)k1 & 3u) == tag)) break;
            }

            // reduce 64 keys: pair-max, then hi/lo REDUX trick
            u64 m = (k0 > k1) ? k0 : k1;
            u32 mhi = __reduce_max_sync(0xffffffffu, (u32)(m >> 32));
            u32 mlo = __reduce_max_sync(0xffffffffu,
                                        ((u32)(m >> 32) == mhi) ? (u32)m : 0u);
            const int f = 8191 - (int)(mlo >> 2);

            ncx = sneg[3 * f + 0];   // broadcast LDS.64
            ncy = sneg[3 * f + 1];
            ncz = sneg[3 * f + 2];
        }
        return;
    }

    // ============================ BALL path ================================
    // block j: batch = j&7, chunk = j>>3 (batch-major interleave so early
    // blocks cover the earliest centroids of every batch).
    {
        const int j     = bid - NFPS - NPREP;
        const int b     = j & 7;
        const int chunk = j >> 3;
        const int m     = chunk * BALLW + w;          // centroid in batch
        const int gw    = b * NPOINT + m;

        float4* sxyz = (float4*)dynsmem;              // 16KB tile
        int (*sel)[NSAMPLE] = (int(*)[NSAMPLE])(dynsmem + 2048);

        // wait until prep done AND our 16 centroids are published
        if (tid == 0) {
            const int need = chunk * BALLW + BALLW;
            int p;
            do {
                asm volatile("ld.acquire.gpu.global.s32 %0, [%1];"
                             : "=r"(p) : "l"(&g_prep_done) : "memory");
                if (p < NPREP) __nanosleep(256);
            } while (p < NPREP);
            do {
                asm volatile("ld.acquire.gpu.global.s32 %0, [%1];"
                             : "=r"(p) : "l"(&g_progress[b]) : "memory");
                if (p < need) __nanosleep(256);
            } while (p < need);
        }
        __syncthreads();

        const float4* pk = g_pk + (size_t)b * NN;
        // L1-bypassing centroid read (line may be cached stale by a neighbor)
        const float* c = new_xyz + (size_t)gw * 3;
        const float sx = __ldcg(c + 0), sy = __ldcg(c + 1), sz = __ldcg(c + 2);
        const float sn = __fadd_rn(__fadd_rn(__fmul_rn(sx, sx), __fmul_rn(sy, sy)),
                                   __fmul_rn(sz, sz));

        int cnt = 0;
        bool done = false;
        const int TILE = 1024;
        for (int t = 0; t < NN / TILE; t++) {
            if (__syncthreads_and(done ? 1 : 0)) break;
            {   // cooperative coalesced tile load: 1024 float4, 2 per thread
                const float4* src = pk + t * TILE;
                sxyz[tid]       = __ldg(src + tid);
                sxyz[tid + 512] = __ldg(src + tid + 512);
            }
            __syncthreads();
            if (!done) {
                for (int base = 0; base < TILE; base += 32) {
                    float4 v = sxyz[base + lane];
                    // sqr = (-2*dot + |src|^2) + |dst|^2
                    float dot = __fadd_rn(__fadd_rn(__fmul_rn(sx, v.x), __fmul_rn(sy, v.y)),
                                          __fmul_rn(sz, v.z));
                    float q = __fadd_rn(__fadd_rn(__fmul_rn(-2.0f, dot), sn), v.w);
                    bool ok = (q <= R2);
                    unsigned msk = __ballot_sync(0xffffffffu, ok);
                    if (ok) {
                        int p = cnt + __popc(msk & ((1u << lane) - 1u));
                        if (p < NSAMPLE) sel[w][p] = t * TILE + base + lane;
                    }
                    cnt += __popc(msk);
                    if (cnt >= NSAMPLE) { done = true; break; }
                }
            }
        }
        __syncwarp();

        // pad with first qualifying index (centroid itself always qualifies)
        int cfull = cnt < NSAMPLE ? cnt : NSAMPLE;
        int first = sel[w][0];
        __syncwarp();
        if (lane >= cfull) sel[w][lane] = first;
        __syncwarp();

        float* op = new_points + (size_t)gw * NSAMPLE * OUTCH;

        // centered xyz: one LDG.128 per lane's own sample
        {
            const int idx = sel[w][lane];
            float4 v = __ldg(pk + idx);
            op[lane * OUTCH + 0] = __fsub_rn(v.x, sx);
            op[lane * OUTCH + 1] = __fsub_rn(v.y, sy);
            op[lane * OUTCH + 2] = __fsub_rn(v.z, sz);
        }

        // features: per sample the warp reads one 256B row coalesced
        const float* pb = points + (size_t)b * NN * DD;
#pragma unroll 4
        for (int s = 0; s < NSAMPLE; s++) {
            int is = sel[w][s];                       // smem broadcast
            float2 v = __ldg((const float2*)(pb + (size_t)is * DD) + lane);
            op[s * OUTCH + 3 + 2 * lane]     = v.x;
            op[s * OUTCH + 3 + 2 * lane + 1] = v.y;
        }
    }
}

// ---------------------------------------------------------------------------
extern "C" void kernel_launch(void* const* d_in, const int* in_sizes, int n_in,
                              void* d_out, int out_size) {
    const float* xyz    = (const float*)d_in[0];
    const float* points = (const float*)d_in[1];

    float* new_xyz    = (float*)d_out;
    float* new_points = (float*)d_out + (size_t)BB * NPOINT * 3;

    cudaFuncSetAttribute(mega_kernel,
                         cudaFuncAttributeMaxDynamicSharedMemorySize, DYN_SMEM);

    init_kernel<<<1, 32>>>();
    mega_kernel<<<NFPS + NPREP + NBALL, FPS_T, DYN_SMEM>>>(xyz, points,
                                                           new_xyz, new_points);
}

// round 16
// speedup vs baseline: 2.2692x; 2.2692x over previous
#include <cuda_runtime.h>
#include <cstdint>

// Problem constants (fixed by setup_inputs)
#define BB 8
#define NN 8192
#define NPOINT 1024
#define NSAMPLE 32
#define DD 64
#define R2 0.0625f
#define OUTCH 67  // 3 + 64

#define FPS_T 512               // threads per block (uniform)
#define CL 4                    // cluster size = FPS CTAs per batch
#define NFPS (BB * CL)          // 32 FPS blocks
#define PTS_CTA (NN / CL)       // 2048 points per FPS CTA
#define NPREP 128               // prep blocks (512 pts each)
#define BALLW 16                // warps (= centroids) per ball block
#define NBALL (BB * NPOINT / BALLW)   // 512 ball blocks
#define DYN_SMEM 196608         // 192KB for every block -> 1 block/SM
#define PUB 16                  // FPS progress publish granularity

using u64 = unsigned long long;
using u32 = unsigned int;

// ---- packed f32x2 helpers (per-lane IEEE RN, bit-identical to scalar RN ops)
__device__ __forceinline__ u64 pk2(float lo, float hi) {
    u64 r; asm("mov.b64 %0, {%1,%2};" : "=l"(r) : "f"(lo), "f"(hi)); return r;
}
__device__ __forceinline__ void up2(u64 v, float& lo, float& hi) {
    asm("mov.b64 {%0,%1}, %2;" : "=f"(lo), "=f"(hi) : "l"(v));
}
__device__ __forceinline__ u64 add2(u64 a, u64 b) {
    u64 r; asm("add.rn.f32x2 %0, %1, %2;" : "=l"(r) : "l"(a), "l"(b)); return r;
}
__device__ __forceinline__ u64 mul2(u64 a, u64 b) {
    u64 r; asm("mul.rn.f32x2 %0, %1, %2;" : "=l"(r) : "l"(a), "l"(b)); return r;
}
__device__ __forceinline__ u32 smem_u32(const void* p) {
    u32 a;
    asm("{ .reg .u64 t; cvta.to.shared.u64 t, %1; cvt.u32.u64 %0, t; }"
        : "=r"(a) : "l"(p));
    return a;
}
__device__ __forceinline__ u32 mapa_u32(u32 a, u32 rank) {
    u32 o; asm("mapa.shared::cluster.u32 %0, %1, %2;" : "=r"(o) : "r"(a), "r"(rank));
    return o;
}
__device__ __forceinline__ void vsts64(u32 a, u64 v) {
    asm volatile("st.volatile.shared.b64 [%0], %1;" :: "r"(a), "l"(v) : "memory");
}
__device__ __forceinline__ void st_cluster64(u32 a, u64 v) {
    asm volatile("st.shared::cluster.b64 [%0], %1;" :: "r"(a), "l"(v) : "memory");
}

// ---------------------------------------------------------------------------
// Device scratch + producer/consumer counters (zeroed per launch by init)
// ---------------------------------------------------------------------------
__device__ float4 g_pk[BB * NN];   // packed {x,y,z,|p|^2}
__device__ int    g_progress[BB];  // FPS steps published per batch
__device__ int    g_prep_done;     // prep blocks completed

__global__ void init_kernel() {
    if (threadIdx.x < BB) g_progress[threadIdx.x] = 0;
    if (threadIdx.x == BB) g_prep_done = 0;
}

// ---------------------------------------------------------------------------
// Mega kernel, cluster size 4. Blocks 0..31: FPS. 32..159: prep. 160..671:
// ball. FPS clusters are exactly blocks 4c..4c+3, so prep/ball clusters never
// execute cluster ops.
//
// FPS: BARRIER-FREE warp-key all-to-all — the R12 topology, which is the
// measured optimum of this design space:
//   * all-warps-poll at CL=8 saturates smem ports (R13: L1 16.9%->40.6%)
//   * designated-poller adds a serial hop (+55us, R14)
//   * per-lane (divergent) polling thrashes BSSY/BSYNC (2x, R15)
//   * mapa-to-own-rank store loses the local-visibility fast path (R15)
// Single change vs R12: the OWN slot is still written locally by lane0
// (vsts64), but the 3 REMOTE posts are issued by lanes 1..3 in parallel
// (REDUX results are warp-uniform), removing lane0's 4-store serialization.
//
//  - key = (val<<32) | ((8191-idx)<<2) | (it&3); aligned 8B store = atomic;
//    key IS the payload -> no fence of any scope, no per-step barrier.
//  - max key = max value, ties -> max(8191-idx) = smallest index =
//    jnp.argmax first-occurrence (tag bits equal across a step).
//  - slot-reuse safety: double-buffered by it&1 with 2-bit tag; buffer b's
//    consecutive users are steps it, it+2 with different tags; a writer
//    reaches it+2 only after consuming it+1, which transitively requires
//    every warp to have consumed it. Slots init to tag=2; one startup
//    cluster.sync covers initialization.
// ---------------------------------------------------------------------------
__global__ void __launch_bounds__(FPS_T, 1) __cluster_dims__(CL, 1, 1)
mega_kernel(const float* __restrict__ xyz, const float* __restrict__ points,
            float* __restrict__ new_xyz, float* __restrict__ new_points) {
    extern __shared__ u64 dynsmem[];
    const int bid = blockIdx.x;
    const int tid = threadIdx.x;
    const int lane = tid & 31;
    const int w    = tid >> 5;

    // =========================== PREP path ================================
    if (bid >= NFPS && bid < NFPS + NPREP) {
        int i = (bid - NFPS) * FPS_T + tid;      // 0 .. BB*NN-1
        const float* p = xyz + (size_t)i * 3;
        float x = __ldg(p + 0), y = __ldg(p + 1), z = __ldg(p + 2);
        float dn = __fadd_rn(__fadd_rn(__fmul_rn(x, x), __fmul_rn(y, y)),
                             __fmul_rn(z, z));
        g_pk[i] = make_float4(x, y, z, dn);
        __syncthreads();
        if (tid == 0) {
            int dummy;
            asm volatile("atom.add.release.gpu.global.s32 %0, [%1], 1;"
                         : "=r"(dummy) : "l"(&g_prep_done) : "memory");
        }
        return;
    }

    // ============================ FPS path =================================
    if (bid < NFPS) {
        u64* sneg = dynsmem;                      // [NN*3] negated dup table
        __shared__ u64 slots[2][64];              // [buf][cta*16+warp]

        const int b       = bid >> 2;
        const u32 rank    = bid & 3;
        const int pbase   = rank * PTS_CTA;
        const float* xb   = xyz + (size_t)b * NN * 3;

        // full-batch negated table (every CTA keeps its own copy)
        for (int j = tid; j < NN; j += FPS_T) {
            float x = __ldg(xb + j * 3 + 0);
            float y = __ldg(xb + j * 3 + 1);
            float z = __ldg(xb + j * 3 + 2);
            sneg[3 * j + 0] = pk2(-x, -x);
            sneg[3 * j + 1] = pk2(-y, -y);
            sneg[3 * j + 2] = pk2(-z, -z);
        }
        // own 4 points (k = 0..3 at pbase + tid + k*512), packed by pairs
        u64 px2[2], py2[2], pz2[2];
        u32 du[4];
#pragma unroll
        for (int p = 0; p < 2; p++) {
            int j0 = pbase + tid + (2 * p) * FPS_T;
            int j1 = pbase + tid + (2 * p + 1) * FPS_T;
            px2[p] = pk2(__ldg(xb + j0 * 3 + 0), __ldg(xb + j1 * 3 + 0));
            py2[p] = pk2(__ldg(xb + j0 * 3 + 1), __ldg(xb + j1 * 3 + 1));
            pz2[p] = pk2(__ldg(xb + j0 * 3 + 2), __ldg(xb + j1 * 3 + 2));
        }
#pragma unroll
        for (int k = 0; k < 4; k++) du[k] = __float_as_uint(1e10f);

        const u32 rbase = smem_u32(&slots[0][0]);
        if (tid < 64) {                    // init both buffers with tag=2
            vsts64(rbase + tid * 8u, 2ull);
            vsts64(rbase + 512u + tid * 8u, 2ull);
        }
        // lanes 1..3: remote peer base (rank+lane mod 4, never own rank)
        const u32 rtgt = mapa_u32(rbase, (rank + (u32)lane) & 3);

        __syncthreads();
        // one-time cluster rendezvous: all CTAs' slots initialized before any
        // remote key write can land
        asm volatile("barrier.cluster.arrive.aligned;" ::: "memory");
        asm volatile("barrier.cluster.wait.aligned;"   ::: "memory");

        u64 ncx = sneg[0], ncy = sneg[1], ncz = sneg[2];   // centroid 0, neg
        float* ob = new_xyz + (size_t)b * NPOINT * 3;
        const bool emitter = (rank == 0) && (tid == FPS_T - 1);
        const u32 myslot = (u32)((rank * 16 + w) << 3);

        for (int it = 0; it < NPOINT; it++) {
            if (emitter) {   // emit un-negated centroid (sign XOR: exact)
                float lx, t0, ly, t1, lz, t2;
                up2(ncx, lx, t0); up2(ncy, ly, t1); up2(ncz, lz, t2);
                ob[it * 3 + 0] = __uint_as_float(__float_as_uint(lx) ^ 0x80000000u);
                ob[it * 3 + 1] = __uint_as_float(__float_as_uint(ly) ^ 0x80000000u);
                ob[it * 3 + 2] = __uint_as_float(__float_as_uint(lz) ^ 0x80000000u);
                if (((it + 1) & (PUB - 1)) == 0) {
                    asm volatile("st.release.gpu.global.s32 [%0], %1;"
                                 :: "l"(&g_progress[b]), "r"(it + 1) : "memory");
                }
            }
            if (it == NPOINT - 1) break;

            // exact jnp order: d = ((dx*dx+dy*dy)+dz*dz); dist = min(dist, d)
#pragma unroll
            for (int p = 0; p < 2; p++) {
                u64 dx = add2(px2[p], ncx);
                u64 dy = add2(py2[p], ncy);
                u64 dz = add2(pz2[p], ncz);
                u64 dd = add2(add2(mul2(dx, dx), mul2(dy, dy)), mul2(dz, dz));
                float a, bq; up2(dd, a, bq);
                du[2 * p]     = min(du[2 * p],     __float_as_uint(a));
                du[2 * p + 1] = min(du[2 * p + 1], __float_as_uint(bq));
            }

            // argmax tree over 4 ('>=' keeps left -> smallest k on ties)
            u32 v01 = max(du[0], du[1]); int k01 = (du[0] >= du[1]) ? 0 : 1;
            u32 v23 = max(du[2], du[3]); int k23 = (du[2] >= du[3]) ? 2 : 3;
            u32 vb  = max(v01, v23);     int kk  = (v01 >= v23) ? k01 : k23;
            u32 idx = (u32)(pbase + tid + kk * FPS_T);

            // warp: max value, then min index among holders of the max
            u32 wmax = __reduce_max_sync(0xffffffffu, vb);
            u32 cand = (vb == wmax) ? idx : 0xffffffffu;
            u32 ci   = __reduce_min_sync(0xffffffffu, cand);

            const u32 boff = (u32)((it & 1) << 9);
            const u32 tag  = (u32)(it & 3);
            // key is warp-uniform: lane0 stores locally (fast local port),
            // lanes 1..3 post to the 3 remote CTAs in parallel
            u64 key = ((u64)wmax << 32) | (u64)(((8191u - ci) << 2) | tag);
            if (lane == 0) {
                vsts64(rbase + boff + myslot, key);
            } else if (lane < 4) {
                st_cluster64(rtgt + boff + myslot, key);
            }

            // poll all 64 slots (2 per lane), uniform exit via __all_sync
            const u32 pa = rbase + boff + (u32)(lane << 4);
            u64 k0, k1;
            for (;;) {
                asm volatile("ld.volatile.shared.v2.u64 {%0,%1}, [%2];"
                             : "=l"(k0), "=l"(k1) : "r"(pa));
                bool ok = (((u32)k0 & 3u) == tag) & (((u32)k1 & 3u) == tag);
                if (__all_sync(0xffffffffu, ok)) break;
            }

            // reduce 64 keys: pair-max, then hi/lo REDUX trick
            u64 m = (k0 > k1) ? k0 : k1;
            u32 mhi = __reduce_max_sync(0xffffffffu, (u32)(m >> 32));
            u32 mlo = __reduce_max_sync(0xffffffffu,
                                        ((u32)(m >> 32) == mhi) ? (u32)m : 0u);
            const int f = 8191 - (int)(mlo >> 2);

            ncx = sneg[3 * f + 0];   // broadcast LDS.64
            ncy = sneg[3 * f + 1];
            ncz = sneg[3 * f + 2];
        }
        return;
    }

    // ============================ BALL path ================================
    // block j: batch = j&7, chunk = j>>3 (batch-major interleave so early
    // blocks cover the earliest centroids of every batch).
    {
        const int j     = bid - NFPS - NPREP;
        const int b     = j & 7;
        const int chunk = j >> 3;
        const int m     = chunk * BALLW + w;          // centroid in batch
        const int gw    = b * NPOINT + m;

        float4* sxyz = (float4*)dynsmem;              // 16KB tile
        int (*sel)[NSAMPLE] = (int(*)[NSAMPLE])(dynsmem + 2048);

        // wait until prep done AND our 16 centroids are published
        if (tid == 0) {
            const int need = chunk * BALLW + BALLW;
            int p;
            do {
                asm volatile("ld.acquire.gpu.global.s32 %0, [%1];"
                             : "=r"(p) : "l"(&g_prep_done) : "memory");
                if (p < NPREP) __nanosleep(256);
            } while (p < NPREP);
            do {
                asm volatile("ld.acquire.gpu.global.s32 %0, [%1];"
                             : "=r"(p) : "l"(&g_progress[b]) : "memory");
                if (p < need) __nanosleep(256);
            } while (p < need);
        }
        __syncthreads();

        const float4* pk = g_pk + (size_t)b * NN;
        // L1-bypassing centroid read (line may be cached stale by a neighbor)
        const float* c = new_xyz + (size_t)gw * 3;
        const float sx = __ldcg(c + 0), sy = __ldcg(c + 1), sz = __ldcg(c + 2);
        const float sn = __fadd_rn(__fadd_rn(__fmul_rn(sx, sx), __fmul_rn(sy, sy)),
                                   __fmul_rn(sz, sz));

        int cnt = 0;
        bool done = false;
        const int TILE = 1024;
        for (int t = 0; t < NN / TILE; t++) {
            if (__syncthreads_and(done ? 1 : 0)) break;
            {   // cooperative coalesced tile load: 1024 float4, 2 per thread
                const float4* src = pk + t * TILE;
                sxyz[tid]       = __ldg(src + tid);
                sxyz[tid + 512] = __ldg(src + tid + 512);
            }
            __syncthreads();
            if (!done) {
                for (int base = 0; base < TILE; base += 32) {
                    float4 v = sxyz[base + lane];
                    // sqr = (-2*dot + |src|^2) + |dst|^2
                    float dot = __fadd_rn(__fadd_rn(__fmul_rn(sx, v.x), __fmul_rn(sy, v.y)),
                                          __fmul_rn(sz, v.z));
                    float q = __fadd_rn(__fadd_rn(__fmul_rn(-2.0f, dot), sn), v.w);
                    bool ok = (q <= R2);
                    unsigned msk = __ballot_sync(0xffffffffu, ok);
                    if (ok) {
                        int p = cnt + __popc(msk & ((1u << lane) - 1u));
                        if (p < NSAMPLE) sel[w][p] = t * TILE + base + lane;
                    }
                    cnt += __popc(msk);
                    if (cnt >= NSAMPLE) { done = true; break; }
                }
            }
        }
        __syncwarp();

        // pad with first qualifying index (centroid itself always qualifies)
        int cfull = cnt < NSAMPLE ? cnt : NSAMPLE;
        int first = sel[w][0];
        __syncwarp();
        if (lane >= cfull) sel[w][lane] = first;
        __syncwarp();

        float* op = new_points + (size_t)gw * NSAMPLE * OUTCH;

        // centered xyz: one LDG.128 per lane's own sample
        {
            const int idx = sel[w][lane];
            float4 v = __ldg(pk + idx);
            op[lane * OUTCH + 0] = __fsub_rn(v.x, sx);
            op[lane * OUTCH + 1] = __fsub_rn(v.y, sy);
            op[lane * OUTCH + 2] = __fsub_rn(v.z, sz);
        }

        // features: per sample the warp reads one 256B row coalesced
        const float* pb = points + (size_t)b * NN * DD;
#pragma unroll 4
        for (int s = 0; s < NSAMPLE; s++) {
            int is = sel[w][s];                       // smem broadcast
            float2 v = __ldg((const float2*)(pb + (size_t)is * DD) + lane);
            op[s * OUTCH + 3 + 2 * lane]     = v.x;
            op[s * OUTCH + 3 + 2 * lane + 1] = v.y;
        }
    }
}

// ---------------------------------------------------------------------------
extern "C" void kernel_launch(void* const* d_in, const int* in_sizes, int n_in,
                              void* d_out, int out_size) {
    const float* xyz    = (const float*)d_in[0];
    const float* points = (const float*)d_in[1];

    float* new_xyz    = (float*)d_out;
    float* new_points = (float*)d_out + (size_t)BB * NPOINT * 3;

    cudaFuncSetAttribute(mega_kernel,
                         cudaFuncAttributeMaxDynamicSharedMemorySize, DYN_SMEM);

    init_kernel<<<1, 32>>>();
    mega_kernel<<<NFPS + NPREP + NBALL, FPS_T, DYN_SMEM>>>(xyz, points,
                                                           new_xyz, new_points);
}

// round 17
// speedup vs baseline: 2.4829x; 1.0942x over previous
#include <cuda_runtime.h>
#include <cstdint>

// Problem constants (fixed by setup_inputs)
#define BB 8
#define NN 8192
#define NPOINT 1024
#define NSAMPLE 32
#define DD 64
#define R2 0.0625f
#define OUTCH 67  // 3 + 64

#define FPS_T 512               // threads per block (uniform)
#define CL 4                    // cluster size = FPS CTAs per batch
#define NFPS (BB * CL)          // 32 FPS blocks
#define PTS_CTA (NN / CL)       // 2048 points per FPS CTA
#define NPREP 128               // prep blocks (512 pts each)
#define BALLW 16                // warps (= centroids) per ball block
#define NBALL (BB * NPOINT / BALLW)   // 512 ball blocks
#define DYN_SMEM 196608         // 192KB for every block -> 1 block/SM
#define PUB 16                  // FPS progress publish granularity

using u64 = unsigned long long;
using u32 = unsigned int;

// ---- packed f32x2 helpers (per-lane IEEE RN, bit-identical to scalar RN ops)
__device__ __forceinline__ u64 pk2(float lo, float hi) {
    u64 r; asm("mov.b64 %0, {%1,%2};" : "=l"(r) : "f"(lo), "f"(hi)); return r;
}
__device__ __forceinline__ void up2(u64 v, float& lo, float& hi) {
    asm("mov.b64 {%0,%1}, %2;" : "=f"(lo), "=f"(hi) : "l"(v));
}
__device__ __forceinline__ u64 add2(u64 a, u64 b) {
    u64 r; asm("add.rn.f32x2 %0, %1, %2;" : "=l"(r) : "l"(a), "l"(b)); return r;
}
__device__ __forceinline__ u64 mul2(u64 a, u64 b) {
    u64 r; asm("mul.rn.f32x2 %0, %1, %2;" : "=l"(r) : "l"(a), "l"(b)); return r;
}
__device__ __forceinline__ u32 smem_u32(const void* p) {
    u32 a;
    asm("{ .reg .u64 t; cvta.to.shared.u64 t, %1; cvt.u32.u64 %0, t; }"
        : "=r"(a) : "l"(p));
    return a;
}
__device__ __forceinline__ u32 mapa_u32(u32 a, u32 rank) {
    u32 o; asm("mapa.shared::cluster.u32 %0, %1, %2;" : "=r"(o) : "r"(a), "r"(rank));
    return o;
}
__device__ __forceinline__ void vsts64(u32 a, u64 v) {
    asm volatile("st.volatile.shared.b64 [%0], %1;" :: "r"(a), "l"(v) : "memory");
}
__device__ __forceinline__ void st_cluster64(u32 a, u64 v) {
    asm volatile("st.shared::cluster.b64 [%0], %1;" :: "r"(a), "l"(v) : "memory");
}

// ---------------------------------------------------------------------------
// Device scratch + producer/consumer counters (zeroed per launch by init)
// ---------------------------------------------------------------------------
__device__ float4 g_pk[BB * NN];   // packed {x,y,z,|p|^2}
__device__ int    g_progress[BB];  // FPS steps published per batch
__device__ int    g_prep_done;     // prep blocks completed

__global__ void init_kernel() {
    if (threadIdx.x < BB) g_progress[threadIdx.x] = 0;
    if (threadIdx.x == BB) g_prep_done = 0;
}

// ---------------------------------------------------------------------------
// Mega kernel, cluster size 4. Blocks 0..31: FPS. 32..159: prep. 160..671:
// ball. FPS clusters are exactly blocks 4c..4c+3, so prep/ball clusters never
// execute cluster ops.
//
// FPS: BARRIER-FREE warp-key all-to-all — the R12/R16 topology (measured
// optimum: all-warps-poll at CL=8 saturates smem ports; designated-poller
// adds a serial hop; divergent polling thrashes BSSY/BSYNC; mapa-to-own-rank
// loses the local fast path). R16's posting split (lane0 local vsts64,
// lanes 1..3 remote st.shared::cluster) retained.
//
// R17 change: EMISSION IN THE FLIGHT SHADOW. The DSMEM cross-CTA flight is
// ~190ns (~400 NAT cycles) and every step paces on the slowest of 64 warps;
// the emitter warp's 3 STG + periodic st.release.gpu used to sit at the top
// of the loop ON the critical path. They now issue immediately after the key
// post, fully hidden under the poll wait. Loop runs it=0..1022; centroid
// 1023 + final release-publish(1024) emitted after the loop (same values,
// same release ordering for ball consumers).
//
//  - key = (val<<32) | ((8191-idx)<<2) | (it&3); aligned 8B store = atomic;
//    key IS the payload -> no fence of any scope, no per-step barrier.
//  - max key = max value, ties -> max(8191-idx) = smallest index =
//    jnp.argmax first-occurrence (tag bits equal across a step).
//  - slot-reuse safety: double-buffered by it&1 with 2-bit tag; buffer b's
//    consecutive users are steps it, it+2 with different tags; a writer
//    reaches it+2 only after consuming it+1, which transitively requires
//    every warp to have consumed it. Slots init to tag=2; one startup
//    cluster.sync covers initialization.
// ---------------------------------------------------------------------------
__global__ void __launch_bounds__(FPS_T, 1) __cluster_dims__(CL, 1, 1)
mega_kernel(const float* __restrict__ xyz, const float* __restrict__ points,
            float* __restrict__ new_xyz, float* __restrict__ new_points) {
    extern __shared__ u64 dynsmem[];
    const int bid = blockIdx.x;
    const int tid = threadIdx.x;
    const int lane = tid & 31;
    const int w    = tid >> 5;

    // =========================== PREP path ================================
    if (bid >= NFPS && bid < NFPS + NPREP) {
        int i = (bid - NFPS) * FPS_T + tid;      // 0 .. BB*NN-1
        const float* p = xyz + (size_t)i * 3;
        float x = __ldg(p + 0), y = __ldg(p + 1), z = __ldg(p + 2);
        float dn = __fadd_rn(__fadd_rn(__fmul_rn(x, x), __fmul_rn(y, y)),
                             __fmul_rn(z, z));
        g_pk[i] = make_float4(x, y, z, dn);
        __syncthreads();
        if (tid == 0) {
            int dummy;
            asm volatile("atom.add.release.gpu.global.s32 %0, [%1], 1;"
                         : "=r"(dummy) : "l"(&g_prep_done) : "memory");
        }
        return;
    }

    // ============================ FPS path =================================
    if (bid < NFPS) {
        u64* sneg = dynsmem;                      // [NN*3] negated dup table
        __shared__ u64 slots[2][64];              // [buf][cta*16+warp]

        const int b       = bid >> 2;
        const u32 rank    = bid & 3;
        const int pbase   = rank * PTS_CTA;
        const float* xb   = xyz + (size_t)b * NN * 3;

        // full-batch negated table (every CTA keeps its own copy)
        for (int j = tid; j < NN; j += FPS_T) {
            float x = __ldg(xb + j * 3 + 0);
            float y = __ldg(xb + j * 3 + 1);
            float z = __ldg(xb + j * 3 + 2);
            sneg[3 * j + 0] = pk2(-x, -x);
            sneg[3 * j + 1] = pk2(-y, -y);
            sneg[3 * j + 2] = pk2(-z, -z);
        }
        // own 4 points (k = 0..3 at pbase + tid + k*512), packed by pairs
        u64 px2[2], py2[2], pz2[2];
        u32 du[4];
#pragma unroll
        for (int p = 0; p < 2; p++) {
            int j0 = pbase + tid + (2 * p) * FPS_T;
            int j1 = pbase + tid + (2 * p + 1) * FPS_T;
            px2[p] = pk2(__ldg(xb + j0 * 3 + 0), __ldg(xb + j1 * 3 + 0));
            py2[p] = pk2(__ldg(xb + j0 * 3 + 1), __ldg(xb + j1 * 3 + 1));
            pz2[p] = pk2(__ldg(xb + j0 * 3 + 2), __ldg(xb + j1 * 3 + 2));
        }
#pragma unroll
        for (int k = 0; k < 4; k++) du[k] = __float_as_uint(1e10f);

        const u32 rbase = smem_u32(&slots[0][0]);
        if (tid < 64) {                    // init both buffers with tag=2
            vsts64(rbase + tid * 8u, 2ull);
            vsts64(rbase + 512u + tid * 8u, 2ull);
        }
        // lanes 1..3: remote peer base (rank+lane mod 4, never own rank)
        const u32 rtgt = mapa_u32(rbase, (rank + (u32)lane) & 3);

        __syncthreads();
        // one-time cluster rendezvous: all CTAs' slots initialized before any
        // remote key write can land
        asm volatile("barrier.cluster.arrive.aligned;" ::: "memory");
        asm volatile("barrier.cluster.wait.aligned;"   ::: "memory");

        u64 ncx = sneg[0], ncy = sneg[1], ncz = sneg[2];   // centroid 0, neg
        float* ob = new_xyz + (size_t)b * NPOINT * 3;
        const bool emitter = (rank == 0) && (tid == FPS_T - 1);
        const u32 myslot = (u32)((rank * 16 + w) << 3);

        for (int it = 0; it < NPOINT - 1; it++) {
            // exact jnp order: d = ((dx*dx+dy*dy)+dz*dz); dist = min(dist, d)
#pragma unroll
            for (int p = 0; p < 2; p++) {
                u64 dx = add2(px2[p], ncx);
                u64 dy = add2(py2[p], ncy);
                u64 dz = add2(pz2[p], ncz);
                u64 dd = add2(add2(mul2(dx, dx), mul2(dy, dy)), mul2(dz, dz));
                float a, bq; up2(dd, a, bq);
                du[2 * p]     = min(du[2 * p],     __float_as_uint(a));
                du[2 * p + 1] = min(du[2 * p + 1], __float_as_uint(bq));
            }

            // argmax tree over 4 ('>=' keeps left -> smallest k on ties)
            u32 v01 = max(du[0], du[1]); int k01 = (du[0] >= du[1]) ? 0 : 1;
            u32 v23 = max(du[2], du[3]); int k23 = (du[2] >= du[3]) ? 2 : 3;
            u32 vb  = max(v01, v23);     int kk  = (v01 >= v23) ? k01 : k23;
            u32 idx = (u32)(pbase + tid + kk * FPS_T);

            // warp: max value, then min index among holders of the max
            u32 wmax = __reduce_max_sync(0xffffffffu, vb);
            u32 cand = (vb == wmax) ? idx : 0xffffffffu;
            u32 ci   = __reduce_min_sync(0xffffffffu, cand);

            const u32 boff = (u32)((it & 1) << 9);
            const u32 tag  = (u32)(it & 3);
            // key is warp-uniform: lane0 stores locally (fast local port),
            // lanes 1..3 post to the 3 remote CTAs in parallel
            u64 key = ((u64)wmax << 32) | (u64)(((8191u - ci) << 2) | tag);
            if (lane == 0) {
                vsts64(rbase + boff + myslot, key);
            } else if (lane < 4) {
                st_cluster64(rtgt + boff + myslot, key);
            }

            // EMISSION IN THE FLIGHT SHADOW: the ~400-cycle DSMEM flight is
            // in progress; the emitter's STGs (and the every-16-step release)
            // issue here, off the step's critical path. ncx still holds
            // centroid(it) (updated only at the end of the iteration).
            if (emitter) {
                float lx, t0, ly, t1, lz, t2;
                up2(ncx, lx, t0); up2(ncy, ly, t1); up2(ncz, lz, t2);
                ob[it * 3 + 0] = __uint_as_float(__float_as_uint(lx) ^ 0x80000000u);
                ob[it * 3 + 1] = __uint_as_float(__float_as_uint(ly) ^ 0x80000000u);
                ob[it * 3 + 2] = __uint_as_float(__float_as_uint(lz) ^ 0x80000000u);
                if (((it + 1) & (PUB - 1)) == 0) {
                    asm volatile("st.release.gpu.global.s32 [%0], %1;"
                                 :: "l"(&g_progress[b]), "r"(it + 1) : "memory");
                }
            }

            // poll all 64 slots (2 per lane), uniform exit via __all_sync
            const u32 pa = rbase + boff + (u32)(lane << 4);
            u64 k0, k1;
            for (;;) {
                asm volatile("ld.volatile.shared.v2.u64 {%0,%1}, [%2];"
                             : "=l"(k0), "=l"(k1) : "r"(pa));
                bool ok = (((u32)k0 & 3u) == tag) & (((u32)k1 & 3u) == tag);
                if (__all_sync(0xffffffffu, ok)) break;
            }

            // reduce 64 keys: pair-max, then hi/lo REDUX trick
            u64 m = (k0 > k1) ? k0 : k1;
            u32 mhi = __reduce_max_sync(0xffffffffu, (u32)(m >> 32));
            u32 mlo = __reduce_max_sync(0xffffffffu,
                                        ((u32)(m >> 32) == mhi) ? (u32)m : 0u);
            const int f = 8191 - (int)(mlo >> 2);

            ncx = sneg[3 * f + 0];   // broadcast LDS.64
            ncy = sneg[3 * f + 1];
            ncz = sneg[3 * f + 2];
        }

        // final centroid (index NPOINT-1) + final publish
        if (emitter) {
            float lx, t0, ly, t1, lz, t2;
            up2(ncx, lx, t0); up2(ncy, ly, t1); up2(ncz, lz, t2);
            ob[(NPOINT - 1) * 3 + 0] = __uint_as_float(__float_as_uint(lx) ^ 0x80000000u);
            ob[(NPOINT - 1) * 3 + 1] = __uint_as_float(__float_as_uint(ly) ^ 0x80000000u);
            ob[(NPOINT - 1) * 3 + 2] = __uint_as_float(__float_as_uint(lz) ^ 0x80000000u);
            asm volatile("st.release.gpu.global.s32 [%0], %1;"
                         :: "l"(&g_progress[b]), "r"(NPOINT) : "memory");
        }
        return;
    }

    // ============================ BALL path ================================
    // block j: batch = j&7, chunk = j>>3 (batch-major interleave so early
    // blocks cover the earliest centroids of every batch).
    {
        const int j     = bid - NFPS - NPREP;
        const int b     = j & 7;
        const int chunk = j >> 3;
        const int m     = chunk * BALLW + w;          // centroid in batch
        const int gw    = b * NPOINT + m;

        float4* sxyz = (float4*)dynsmem;              // 16KB tile
        int (*sel)[NSAMPLE] = (int(*)[NSAMPLE])(dynsmem + 2048);

        // wait until prep done AND our 16 centroids are published
        if (tid == 0) {
            const int need = chunk * BALLW + BALLW;
            int p;
            do {
                asm volatile("ld.acquire.gpu.global.s32 %0, [%1];"
                             : "=r"(p) : "l"(&g_prep_done) : "memory");
                if (p < NPREP) __nanosleep(256);
            } while (p < NPREP);
            do {
                asm volatile("ld.acquire.gpu.global.s32 %0, [%1];"
                             : "=r"(p) : "l"(&g_progress[b]) : "memory");
                if (p < need) __nanosleep(256);
            } while (p < need);
        }
        __syncthreads();

        const float4* pk = g_pk + (size_t)b * NN;
        // L1-bypassing centroid read (line may be cached stale by a neighbor)
        const float* c = new_xyz + (size_t)gw * 3;
        const float sx = __ldcg(c + 0), sy = __ldcg(c + 1), sz = __ldcg(c + 2);
        const float sn = __fadd_rn(__fadd_rn(__fmul_rn(sx, sx), __fmul_rn(sy, sy)),
                                   __fmul_rn(sz, sz));

        int cnt = 0;
        bool done = false;
        const int TILE = 1024;
        for (int t = 0; t < NN / TILE; t++) {
            if (__syncthreads_and(done ? 1 : 0)) break;
            {   // cooperative coalesced tile load: 1024 float4, 2 per thread
                const float4* src = pk + t * TILE;
                sxyz[tid]       = __ldg(src + tid);
                sxyz[tid + 512] = __ldg(src + tid + 512);
            }
            __syncthreads();
            if (!done) {
                for (int base = 0; base < TILE; base += 32) {
                    float4 v = sxyz[base + lane];
                    // sqr = (-2*dot + |src|^2) + |dst|^2
                    float dot = __fadd_rn(__fadd_rn(__fmul_rn(sx, v.x), __fmul_rn(sy, v.y)),
                                          __fmul_rn(sz, v.z));
                    float q = __fadd_rn(__fadd_rn(__fmul_rn(-2.0f, dot), sn), v.w);
                    bool ok = (q <= R2);
                    unsigned msk = __ballot_sync(0xffffffffu, ok);
                    if (ok) {
                        int p = cnt + __popc(msk & ((1u << lane) - 1u));
                        if (p < NSAMPLE) sel[w][p] = t * TILE + base + lane;
                    }
                    cnt += __popc(msk);
                    if (cnt >= NSAMPLE) { done = true; break; }
                }
            }
        }
        __syncwarp();

        // pad with first qualifying index (centroid itself always qualifies)
        int cfull = cnt < NSAMPLE ? cnt : NSAMPLE;
        int first = sel[w][0];
        __syncwarp();
        if (lane >= cfull) sel[w][lane] = first;
        __syncwarp();

        float* op = new_points + (size_t)gw * NSAMPLE * OUTCH;

        // centered xyz: one LDG.128 per lane's own sample
        {
            const int idx = sel[w][lane];
            float4 v = __ldg(pk + idx);
            op[lane * OUTCH + 0] = __fsub_rn(v.x, sx);
            op[lane * OUTCH + 1] = __fsub_rn(v.y, sy);
            op[lane * OUTCH + 2] = __fsub_rn(v.z, sz);
        }

        // features: per sample the warp reads one 256B row coalesced
        const float* pb = points + (size_t)b * NN * DD;
#pragma unroll 4
        for (int s = 0; s < NSAMPLE; s++) {
            int is = sel[w][s];                       // smem broadcast
            float2 v = __ldg((const float2*)(pb + (size_t)is * DD) + lane);
            op[s * OUTCH + 3 + 2 * lane]     = v.x;
            op[s * OUTCH + 3 + 2 * lane + 1] = v.y;
        }
    }
}

// ---------------------------------------------------------------------------
extern "C" void kernel_launch(void* const* d_in, const int* in_sizes, int n_in,
                              void* d_out, int out_size) {
    const float* xyz    = (const float*)d_in[0];
    const float* points = (const float*)d_in[1];

    float* new_xyz    = (float*)d_out;
    float* new_points = (float*)d_out + (size_t)BB * NPOINT * 3;

    cudaFuncSetAttribute(mega_kernel,
                         cudaFuncAttributeMaxDynamicSharedMemorySize, DYN_SMEM);

    init_kernel<<<1, 32>>>();
    mega_kernel<<<NFPS + NPREP + NBALL, FPS_T, DYN_SMEM>>>(xyz, points,
                                                           new_xyz, new_points);
}